// round 9
// baseline (speedup 1.0000x reference)
#include <cuda_runtime.h>
#include <math_constants.h>

#define ROWS_OUT 32

// order-preserving float<->uint transforms (monotonic bijection)
__device__ __forceinline__ unsigned ford(float f) {
    int b = __float_as_int(f);
    return (unsigned)(b ^ ((b >> 31) | 0x80000000));
}
__device__ __forceinline__ float funord(unsigned o) {
    int b = (int)o;
    return __int_as_float(b ^ ((~(b >> 31)) | 0x80000000));
}

// i < 0 sentinel ("row -1") -> -2 ; blank -> -1 ; i>1 -> i-1 ; i==1 -> 0
__device__ __forceinline__ int ctc_char(int i) {
    if (i < 0) return -2;
    return (i == 0) ? -1 : ((i > 1) ? (i - 1) : 0);
}

// Load + argmax of one 512-float row; result to ALL lanes.
// First-occurrence tie-break. Streaming loads (no reuse).
__device__ __forceinline__ int argmax_row(const float4* __restrict__ p, int lane) {
    const float4 a = __ldcs(p + lane);
    const float4 b = __ldcs(p + lane + 32);
    const float4 c = __ldcs(p + lane + 64);
    const float4 d = __ldcs(p + lane + 96);

    const float ma = fmaxf(fmaxf(a.x, a.y), fmaxf(a.z, a.w));
    const float mb = fmaxf(fmaxf(b.x, b.y), fmaxf(b.z, b.w));
    const float mc = fmaxf(fmaxf(c.x, c.y), fmaxf(c.z, c.w));
    const float md = fmaxf(fmaxf(d.x, d.y), fmaxf(d.z, d.w));
    const float m  = fmaxf(fmaxf(ma, mb), fmaxf(mc, md));

    const float wmax = funord(__reduce_max_sync(0xffffffffu, ford(m)));

    const int b0 = lane * 4, b1 = (lane + 32) * 4, b2 = (lane + 64) * 4, b3 = (lane + 96) * 4;
    int cand = 0x7fffffff;
    cand = (d.w == wmax) ? b3 + 3 : cand;
    cand = (d.z == wmax) ? b3 + 2 : cand;
    cand = (d.y == wmax) ? b3 + 1 : cand;
    cand = (d.x == wmax) ? b3 + 0 : cand;
    cand = (c.w == wmax) ? b2 + 3 : cand;
    cand = (c.z == wmax) ? b2 + 2 : cand;
    cand = (c.y == wmax) ? b2 + 1 : cand;
    cand = (c.x == wmax) ? b2 + 0 : cand;
    cand = (b.w == wmax) ? b1 + 3 : cand;
    cand = (b.z == wmax) ? b1 + 2 : cand;
    cand = (b.y == wmax) ? b1 + 1 : cand;
    cand = (b.x == wmax) ? b1 + 0 : cand;
    cand = (a.w == wmax) ? b0 + 3 : cand;
    cand = (a.z == wmax) ? b0 + 2 : cand;
    cand = (a.y == wmax) ? b0 + 1 : cand;
    cand = (a.x == wmax) ? b0 + 0 : cand;

    return (int)__reduce_min_sync(0xffffffffu, (unsigned)cand);
}

// Block b (32 warps): outputs rows [32b, 32b+32).
// Warp w (w>=1) -> row 32b + w. Warp 0 -> boundary row 32b-1, then row 32b
// (sequential, keeps regs <= 32 so 2 blocks stay resident per SM).
// Grid = 2048 blocks = 6 full waves + a 272/296 near-full wave (no straggler).
__global__ __launch_bounds__(1024, 2)
void ctc_fused_kernel(const float* __restrict__ em,
                      float* __restrict__ out_index,
                      float* __restrict__ out_keep,
                      int T) {
    __shared__ int s_idx[ROWS_OUT + 1];   // [0] = boundary row, [1+w] = row 32b+w

    const int w    = threadIdx.x >> 5;
    const int lane = threadIdx.x & 31;
    const int base = blockIdx.x * ROWS_OUT;
    const float4* emv = reinterpret_cast<const float4*>(em);

    if (w == 0) {
        int prev = -1;                                  // sentinel for row -1
        if (base > 0)
            prev = argmax_row(emv + (size_t)(base - 1) * 128, lane);
        const int own = argmax_row(emv + (size_t)base * 128, lane);
        if (lane == 0) { s_idx[0] = prev; s_idx[1] = own; }
    } else {
        const int row = base + w;
        int bi = -1;
        if (row < T)
            bi = argmax_row(emv + (size_t)row * 128, lane);
        if (lane == 0) s_idx[w + 1] = bi;
    }
    __syncthreads();

    // coalesced output phase: warp 0, thread i -> output row 32b + i
    if (threadIdx.x < ROWS_OUT) {
        const int t = base + threadIdx.x;
        if (t < T) {
            const int cur = s_idx[threadIdx.x + 1];
            const int prv = s_idx[threadIdx.x];
            const int c  = ctc_char(cur);
            const int pc = ctc_char(prv);
            out_index[t] = (float)cur;
            out_keep[t]  = (c != pc && c != -1) ? 1.0f : 0.0f;
        }
    }
}

extern "C" void kernel_launch(void* const* d_in, const int* in_sizes, int n_in,
                              void* d_out, int out_size) {
    const float* emission = (const float*)d_in[0];
    const int V = 512;
    const int T = in_sizes[0] / V;   // 65536

    float* out = (float*)d_out;      // [0:T] index (as float), [T:2T] keep (0/1)
    float* out_index = out;
    float* out_keep  = out + T;

    const int blocks = (T + ROWS_OUT - 1) / ROWS_OUT;   // 2048
    ctc_fused_kernel<<<blocks, 1024>>>(emission, out_index, out_keep, T);
}

// round 13
// speedup vs baseline: 1.0543x; 1.0543x over previous
#include <cuda_runtime.h>
#include <math_constants.h>

#define ROWS_OUT 32

// order-preserving float<->uint transforms (monotonic bijection)
__device__ __forceinline__ unsigned ford(float f) {
    int b = __float_as_int(f);
    return (unsigned)(b ^ ((b >> 31) | 0x80000000));
}
__device__ __forceinline__ float funord(unsigned o) {
    int b = (int)o;
    return __int_as_float(b ^ ((~(b >> 31)) | 0x80000000));
}

// i < 0 sentinel ("row -1") -> -2 ; blank -> -1 ; i>1 -> i-1 ; i==1 -> 0
__device__ __forceinline__ int ctc_char(int i) {
    if (i < 0) return -2;
    return (i == 0) ? -1 : ((i > 1) ? (i - 1) : 0);
}

// Block b (32 warps, 1024 threads): outputs rows [32b, 32b+32).
// Warp w computes argmax of row 32b + w (4x LDG.128/lane, MLP 4) AND lanes
// 0..15 of each warp load 16 elements of the boundary row 32b-1 (1 extra
// LDG.32). After one sync, warp 0 merges the 32 boundary slices (2 REDUX)
// and writes index+keep coalesced. No warp is serialized; grid = 2048 blocks
// -> 6 full waves + 272/296 near-full wave (no straggler).
__global__ __launch_bounds__(1024, 2)
void ctc_fused_kernel(const float* __restrict__ em,
                      float* __restrict__ out_index,
                      float* __restrict__ out_keep,
                      int T) {
    __shared__ int s_idx[ROWS_OUT];        // argmax of row base+w
    __shared__ unsigned s_bval[ROWS_OUT];  // boundary slice max (ordered uint)
    __shared__ int s_bidx[ROWS_OUT];       // boundary slice argmax col

    const int w    = threadIdx.x >> 5;
    const int lane = threadIdx.x & 31;
    const int base = blockIdx.x * ROWS_OUT;
    const float4* __restrict__ emv = reinterpret_cast<const float4*>(em);

    // ---- boundary row slice: warp w, lanes 0..15 cover cols [16w, 16w+16) ----
    float bv = -CUDART_INF_F;
    if (base > 0 && lane < 16)
        bv = __ldg(em + (size_t)(base - 1) * 512 + w * 16 + lane);

    // ---- main row argmax (front-batched loads) ----
    const int row = base + w;
    const float4* p = emv + (size_t)row * 128;
    const bool vr = (row < T);
    float4 a, b, c, d;
    if (vr) {
        a = __ldg(p + lane);
        b = __ldg(p + lane + 32);
        c = __ldg(p + lane + 64);
        d = __ldg(p + lane + 96);
    }

    int bi = -1;
    if (vr) {
        const float ma = fmaxf(fmaxf(a.x, a.y), fmaxf(a.z, a.w));
        const float mb = fmaxf(fmaxf(b.x, b.y), fmaxf(b.z, b.w));
        const float mc = fmaxf(fmaxf(c.x, c.y), fmaxf(c.z, c.w));
        const float md = fmaxf(fmaxf(d.x, d.y), fmaxf(d.z, d.w));
        const float m  = fmaxf(fmaxf(ma, mb), fmaxf(mc, md));
        const float wmax = funord(__reduce_max_sync(0xffffffffu, ford(m)));

        const int c0 = lane * 4, c1 = (lane + 32) * 4, c2 = (lane + 64) * 4, c3 = (lane + 96) * 4;
        int cand = 0x7fffffff;
        cand = (d.w == wmax) ? c3 + 3 : cand;
        cand = (d.z == wmax) ? c3 + 2 : cand;
        cand = (d.y == wmax) ? c3 + 1 : cand;
        cand = (d.x == wmax) ? c3 + 0 : cand;
        cand = (c.w == wmax) ? c2 + 3 : cand;
        cand = (c.z == wmax) ? c2 + 2 : cand;
        cand = (c.y == wmax) ? c2 + 1 : cand;
        cand = (c.x == wmax) ? c2 + 0 : cand;
        cand = (b.w == wmax) ? c1 + 3 : cand;
        cand = (b.z == wmax) ? c1 + 2 : cand;
        cand = (b.y == wmax) ? c1 + 1 : cand;
        cand = (b.x == wmax) ? c1 + 0 : cand;
        cand = (a.w == wmax) ? c0 + 3 : cand;
        cand = (a.z == wmax) ? c0 + 2 : cand;
        cand = (a.y == wmax) ? c0 + 1 : cand;
        cand = (a.x == wmax) ? c0 + 0 : cand;
        bi = (int)__reduce_min_sync(0xffffffffu, (unsigned)cand);
    }

    // ---- reduce boundary slice within warp (lanes >=16 hold -inf) ----
    const unsigned bvo  = ford(bv);
    const unsigned smax = __reduce_max_sync(0xffffffffu, bvo);
    int scand = 0x7fffffff;
    if (bvo == smax && lane < 16) scand = w * 16 + lane;
    const int sidx = (int)__reduce_min_sync(0xffffffffu, (unsigned)scand);

    if (lane == 0) {
        s_idx[w]  = bi;
        s_bval[w] = smax;
        s_bidx[w] = sidx;
    }
    __syncthreads();

    // ---- warp 0: merge boundary slices, then coalesced output phase ----
    if (threadIdx.x < 32) {
        const unsigned ov = s_bval[threadIdx.x];
        const int      oi = s_bidx[threadIdx.x];
        const unsigned gmax = __reduce_max_sync(0xffffffffu, ov);
        int cand = (ov == gmax) ? oi : 0x7fffffff;
        int bprev = (int)__reduce_min_sync(0xffffffffu, (unsigned)cand);
        if (base == 0) bprev = -1;   // sentinel: row -1

        const int t = base + threadIdx.x;
        if (t < T) {
            const int cur = s_idx[threadIdx.x];
            const int prv = (threadIdx.x == 0) ? bprev : s_idx[threadIdx.x - 1];
            const int cc = ctc_char(cur);
            const int pc = ctc_char(prv);
            out_index[t] = (float)cur;
            out_keep[t]  = (cc != pc && cc != -1) ? 1.0f : 0.0f;
        }
    }
}

extern "C" void kernel_launch(void* const* d_in, const int* in_sizes, int n_in,
                              void* d_out, int out_size) {
    const float* emission = (const float*)d_in[0];
    const int V = 512;
    const int T = in_sizes[0] / V;   // 65536

    float* out = (float*)d_out;      // [0:T] index (as float), [T:2T] keep (0/1)
    float* out_index = out;
    float* out_keep  = out + T;

    const int blocks = (T + ROWS_OUT - 1) / ROWS_OUT;   // 2048
    ctc_fused_kernel<<<blocks, 1024>>>(emission, out_index, out_keep, T);
}